// round 1
// baseline (speedup 1.0000x reference)
#include <cuda_runtime.h>
#include <math.h>

#define NN 30000
#define EE 300000
#define RR 3
#define KIN 256
#define F1 128   // HEADS*HID
#define F2 256   // HEADS*OUT

// ---------------- scratch (device globals; no allocation allowed) ----------
__device__ __align__(16) float g_z1[(size_t)RR * NN * F1];   // 46 MB
__device__ __align__(16) float g_z2[(size_t)RR * NN * F2];   // 92 MB
__device__ __align__(16) float g_h[(size_t)NN * F1];         // 15 MB
__device__ __align__(16) float g_el1[RR * NN * 4];
__device__ __align__(16) float g_er1[RR * NN * 4];
__device__ __align__(16) float g_el2[RR * NN * 4];
__device__ __align__(16) float g_er2[RR * NN * 4];
__device__ int g_deg[RR * NN];
__device__ int g_cur[RR * NN];
__device__ int g_rowoff[RR * (NN + 1)];
__device__ int g_col[RR * EE];

__device__ __forceinline__ float lrelu(float x) { return x > 0.f ? x : 0.2f * x; }

// ---------------- CSR build --------------------------------------------------
__global__ void k_zero() {
    int i = blockIdx.x * blockDim.x + threadIdx.x;
    if (i < RR * NN) { g_deg[i] = 0; g_cur[i] = 0; }
}

__global__ void k_hist(const int* __restrict__ dst) {
    int i = blockIdx.x * blockDim.x + threadIdx.x;
    if (i < RR * EE) {
        int r = i / EE;
        atomicAdd(&g_deg[r * NN + dst[i]], 1);
    }
}

__global__ void k_scan() {   // one block per relation; exclusive scan of degrees
    int r = blockIdx.x;
    __shared__ int sh[1024];
    __shared__ int carry;
    int t = threadIdx.x;
    if (t == 0) { carry = 0; g_rowoff[r * (NN + 1)] = 0; }
    __syncthreads();
    for (int base = 0; base < NN; base += 1024) {
        int i = base + t;
        int v = (i < NN) ? g_deg[r * NN + i] : 0;
        sh[t] = v;
        __syncthreads();
        for (int off = 1; off < 1024; off <<= 1) {
            int x = (t >= off) ? sh[t - off] : 0;
            __syncthreads();
            sh[t] += x;
            __syncthreads();
        }
        if (i < NN) g_rowoff[r * (NN + 1) + i + 1] = carry + sh[t];
        __syncthreads();
        if (t == 0) carry += sh[1023];
        __syncthreads();
    }
}

__global__ void k_scatter(const int* __restrict__ src, const int* __restrict__ dst) {
    int i = blockIdx.x * blockDim.x + threadIdx.x;
    if (i < RR * EE) {
        int r = i / EE;
        int d = dst[i];
        int pos = atomicAdd(&g_cur[r * NN + d], 1);
        g_col[(size_t)r * EE + g_rowoff[r * (NN + 1) + d] + pos] = src[i];
    }
}

// ---------------- SGEMM: C[r] = A @ B[r], row-major --------------------------
// 64x64 tile, BK=16, 256 threads, 4x4 register microtile.
__global__ void k_sgemm(const float* __restrict__ Aext, const float* __restrict__ Bg,
                        int M, int K, int Nc, int layer) {
    const float* A = (layer == 1) ? Aext : g_h;
    float* C = (layer == 1) ? g_z1 : g_z2;
    int r = blockIdx.z;
    const float* B = Bg + (size_t)r * K * Nc;
    C += (size_t)r * M * Nc;

    __shared__ float As[16][68];
    __shared__ float Bs[16][64];

    int tid = threadIdx.x;
    int tx = tid & 15, ty = tid >> 4;
    int row0 = blockIdx.y * 64, col0 = blockIdx.x * 64;

    float acc[4][4];
#pragma unroll
    for (int i = 0; i < 4; i++)
#pragma unroll
        for (int j = 0; j < 4; j++) acc[i][j] = 0.f;

    int la_m = tid >> 4, la_k = tid & 15;   // A loads: coalesced over k
    int lb_n = tid & 63, lb_k = tid >> 6;   // B loads: coalesced over n

    for (int k0 = 0; k0 < K; k0 += 16) {
#pragma unroll
        for (int mm = 0; mm < 4; mm++) {
            int m = la_m + mm * 16;
            int gr = row0 + m;
            As[la_k][m] = (gr < M) ? A[(size_t)gr * K + k0 + la_k] : 0.f;
        }
#pragma unroll
        for (int kk = 0; kk < 4; kk++) {
            int k = lb_k + kk * 4;
            Bs[k][lb_n] = B[(size_t)(k0 + k) * Nc + col0 + lb_n];
        }
        __syncthreads();
#pragma unroll
        for (int k = 0; k < 16; k++) {
            float a[4], b[4];
#pragma unroll
            for (int i = 0; i < 4; i++) a[i] = As[k][ty * 4 + i];
#pragma unroll
            for (int j = 0; j < 4; j++) b[j] = Bs[k][tx * 4 + j];
#pragma unroll
            for (int i = 0; i < 4; i++)
#pragma unroll
                for (int j = 0; j < 4; j++) acc[i][j] += a[i] * b[j];
        }
        __syncthreads();
    }
#pragma unroll
    for (int i = 0; i < 4; i++) {
        int gr = row0 + ty * 4 + i;
        if (gr < M) {
            float4 v = make_float4(acc[i][0], acc[i][1], acc[i][2], acc[i][3]);
            *reinterpret_cast<float4*>(&C[(size_t)gr * Nc + col0 + tx * 4]) = v;
        }
    }
}

// ---------------- attention projections (el/er) ------------------------------
__global__ void k_attn1(const float* __restrict__ al, const float* __restrict__ ar) {
    int n = blockIdx.x, r = blockIdx.y;
    int t = threadIdx.x;  // 128
    float z = g_z1[((size_t)(r * NN + n)) * F1 + t];
    float pl = z * al[r * F1 + t];
    float pr = z * ar[r * F1 + t];
#pragma unroll
    for (int o = 16; o > 0; o >>= 1) {
        pl += __shfl_xor_sync(0xffffffffu, pl, o);
        pr += __shfl_xor_sync(0xffffffffu, pr, o);
    }
    if ((t & 31) == 0) {
        int h = t >> 5;
        g_el1[(r * NN + n) * 4 + h] = pl;
        g_er1[(r * NN + n) * 4 + h] = pr;
    }
}

__global__ void k_attn2(const float* __restrict__ al, const float* __restrict__ ar) {
    int n = blockIdx.x, r = blockIdx.y;
    int t = threadIdx.x;  // 256
    float z = g_z2[((size_t)(r * NN + n)) * F2 + t];
    float pl = z * al[r * F2 + t];
    float pr = z * ar[r * F2 + t];
#pragma unroll
    for (int o = 16; o > 0; o >>= 1) {
        pl += __shfl_xor_sync(0xffffffffu, pl, o);
        pr += __shfl_xor_sync(0xffffffffu, pr, o);
    }
    __shared__ float sl[8], sr[8];
    if ((t & 31) == 0) { sl[t >> 5] = pl; sr[t >> 5] = pr; }
    __syncthreads();
    if (t < 4) {
        g_el2[(r * NN + n) * 4 + t] = sl[2 * t] + sl[2 * t + 1];
        g_er2[(r * NN + n) * 4 + t] = sr[2 * t] + sr[2 * t + 1];
    }
}

// ---------------- layer-1 edge softmax + aggregation (warp per dst node) -----
__global__ void k_agg1(const float* __restrict__ b1) {
    int w = (blockIdx.x * blockDim.x + threadIdx.x) >> 5;
    int lane = threadIdx.x & 31;
    if (w >= NN) return;
    int n = w;
    float t0 = 0.f, t1 = 0.f, t2 = 0.f, t3 = 0.f;
#pragma unroll
    for (int r = 0; r < RR; r++) {
        int beg = g_rowoff[r * (NN + 1) + n];
        int end = g_rowoff[r * (NN + 1) + n + 1];
        if (beg == end) continue;
        const float4 erd = *reinterpret_cast<const float4*>(&g_er1[(r * NN + n) * 4]);
        float m0 = -1e30f, m1 = -1e30f, m2 = -1e30f, m3 = -1e30f;
        for (int i = beg; i < end; i++) {
            int s = g_col[(size_t)r * EE + i];
            float4 el = *reinterpret_cast<const float4*>(&g_el1[(r * NN + s) * 4]);
            m0 = fmaxf(m0, lrelu(el.x + erd.x));
            m1 = fmaxf(m1, lrelu(el.y + erd.y));
            m2 = fmaxf(m2, lrelu(el.z + erd.z));
            m3 = fmaxf(m3, lrelu(el.w + erd.w));
        }
        float d0 = 0, d1 = 0, d2 = 0, d3 = 0, a0 = 0, a1 = 0, a2 = 0, a3 = 0;
        for (int i = beg; i < end; i++) {
            int s = g_col[(size_t)r * EE + i];
            float4 el = *reinterpret_cast<const float4*>(&g_el1[(r * NN + s) * 4]);
            float w0 = expf(lrelu(el.x + erd.x) - m0);
            float w1 = expf(lrelu(el.y + erd.y) - m1);
            float w2 = expf(lrelu(el.z + erd.z) - m2);
            float w3 = expf(lrelu(el.w + erd.w) - m3);
            d0 += w0; d1 += w1; d2 += w2; d3 += w3;
            const float* z = &g_z1[((size_t)(r * NN + s)) * F1];
            a0 += w0 * z[lane];
            a1 += w1 * z[32 + lane];
            a2 += w2 * z[64 + lane];
            a3 += w3 * z[96 + lane];
        }
        t0 += a0 / d0; t1 += a1 / d1; t2 += a2 / d2; t3 += a3 / d3;
    }
    t0 += b1[lane]      + b1[F1 + lane]      + b1[2 * F1 + lane];
    t1 += b1[32 + lane] + b1[F1 + 32 + lane] + b1[2 * F1 + 32 + lane];
    t2 += b1[64 + lane] + b1[F1 + 64 + lane] + b1[2 * F1 + 64 + lane];
    t3 += b1[96 + lane] + b1[F1 + 96 + lane] + b1[2 * F1 + 96 + lane];
    size_t o = (size_t)n * F1;
    g_h[o + lane]      = fmaxf(t0, 0.f);
    g_h[o + 32 + lane] = fmaxf(t1, 0.f);
    g_h[o + 64 + lane] = fmaxf(t2, 0.f);
    g_h[o + 96 + lane] = fmaxf(t3, 0.f);
}

// ---------------- layer-2 edge softmax + aggregation + head mean -------------
__global__ void k_agg2(const float* __restrict__ b2, float* __restrict__ out) {
    int w = (blockIdx.x * blockDim.x + threadIdx.x) >> 5;
    int lane = threadIdx.x & 31;
    if (w >= NN) return;
    int n = w;
    float t00 = 0, t01 = 0, t10 = 0, t11 = 0, t20 = 0, t21 = 0, t30 = 0, t31 = 0;
#pragma unroll
    for (int r = 0; r < RR; r++) {
        int beg = g_rowoff[r * (NN + 1) + n];
        int end = g_rowoff[r * (NN + 1) + n + 1];
        if (beg == end) continue;
        const float4 erd = *reinterpret_cast<const float4*>(&g_er2[(r * NN + n) * 4]);
        float m0 = -1e30f, m1 = -1e30f, m2 = -1e30f, m3 = -1e30f;
        for (int i = beg; i < end; i++) {
            int s = g_col[(size_t)r * EE + i];
            float4 el = *reinterpret_cast<const float4*>(&g_el2[(r * NN + s) * 4]);
            m0 = fmaxf(m0, lrelu(el.x + erd.x));
            m1 = fmaxf(m1, lrelu(el.y + erd.y));
            m2 = fmaxf(m2, lrelu(el.z + erd.z));
            m3 = fmaxf(m3, lrelu(el.w + erd.w));
        }
        float d0 = 0, d1 = 0, d2 = 0, d3 = 0;
        float a00 = 0, a01 = 0, a10 = 0, a11 = 0, a20 = 0, a21 = 0, a30 = 0, a31 = 0;
        for (int i = beg; i < end; i++) {
            int s = g_col[(size_t)r * EE + i];
            float4 el = *reinterpret_cast<const float4*>(&g_el2[(r * NN + s) * 4]);
            float w0 = expf(lrelu(el.x + erd.x) - m0);
            float w1 = expf(lrelu(el.y + erd.y) - m1);
            float w2 = expf(lrelu(el.z + erd.z) - m2);
            float w3 = expf(lrelu(el.w + erd.w) - m3);
            d0 += w0; d1 += w1; d2 += w2; d3 += w3;
            const float* z = &g_z2[((size_t)(r * NN + s)) * F2];
            a00 += w0 * z[lane];        a01 += w0 * z[32 + lane];
            a10 += w1 * z[64 + lane];   a11 += w1 * z[96 + lane];
            a20 += w2 * z[128 + lane];  a21 += w2 * z[160 + lane];
            a30 += w3 * z[192 + lane];  a31 += w3 * z[224 + lane];
        }
        t00 += a00 / d0; t01 += a01 / d0;
        t10 += a10 / d1; t11 += a11 / d1;
        t20 += a20 / d2; t21 += a21 / d2;
        t30 += a30 / d3; t31 += a31 / d3;
    }
    t00 += b2[lane]       + b2[F2 + lane]       + b2[2 * F2 + lane];
    t01 += b2[32 + lane]  + b2[F2 + 32 + lane]  + b2[2 * F2 + 32 + lane];
    t10 += b2[64 + lane]  + b2[F2 + 64 + lane]  + b2[2 * F2 + 64 + lane];
    t11 += b2[96 + lane]  + b2[F2 + 96 + lane]  + b2[2 * F2 + 96 + lane];
    t20 += b2[128 + lane] + b2[F2 + 128 + lane] + b2[2 * F2 + 128 + lane];
    t21 += b2[160 + lane] + b2[F2 + 160 + lane] + b2[2 * F2 + 160 + lane];
    t30 += b2[192 + lane] + b2[F2 + 192 + lane] + b2[2 * F2 + 192 + lane];
    t31 += b2[224 + lane] + b2[F2 + 224 + lane] + b2[2 * F2 + 224 + lane];
    out[(size_t)n * 64 + lane]      = 0.25f * (t00 + t10 + t20 + t30);
    out[(size_t)n * 64 + 32 + lane] = 0.25f * (t01 + t11 + t21 + t31);
}

// ---------------- launch ------------------------------------------------------
extern "C" void kernel_launch(void* const* d_in, const int* in_sizes, int n_in,
                              void* d_out, int out_size) {
    const float* x   = (const float*)d_in[0];
    const int*   src = (const int*)d_in[1];
    const int*   dst = (const int*)d_in[2];
    const float* W1  = (const float*)d_in[3];
    const float* al1 = (const float*)d_in[4];
    const float* ar1 = (const float*)d_in[5];
    const float* b1  = (const float*)d_in[6];
    const float* W2  = (const float*)d_in[7];
    const float* al2 = (const float*)d_in[8];
    const float* ar2 = (const float*)d_in[9];
    const float* b2  = (const float*)d_in[10];
    float* out = (float*)d_out;

    // CSR by dst, per relation
    k_zero<<<(RR * NN + 255) / 256, 256>>>();
    k_hist<<<(RR * EE + 255) / 256, 256>>>(dst);
    k_scan<<<RR, 1024>>>();
    k_scatter<<<(RR * EE + 255) / 256, 256>>>(src, dst);

    // layer 1
    dim3 g1(F1 / 64, (NN + 63) / 64, RR);
    k_sgemm<<<g1, 256>>>(x, W1, NN, KIN, F1, 1);
    k_attn1<<<dim3(NN, RR), 128>>>(al1, ar1);
    k_agg1<<<(NN + 3) / 4, 128>>>(b1);

    // layer 2
    dim3 g2(F2 / 64, (NN + 63) / 64, RR);
    k_sgemm<<<g2, 256>>>(nullptr, W2, NN, F1, F2, 2);
    k_attn2<<<dim3(NN, RR), 256>>>(al2, ar2);
    k_agg2<<<(NN + 3) / 4, 128>>>(b2, out);
}

// round 2
// speedup vs baseline: 1.1794x; 1.1794x over previous
#include <cuda_runtime.h>
#include <math.h>

#define NN 30000
#define EE 300000
#define RR 3
#define KIN 256
#define F1 128   // HEADS*HID
#define F2 256   // HEADS*OUT

// ---------------- scratch (device globals; no allocation allowed) ----------
__device__ __align__(16) float g_z1[(size_t)RR * NN * F1];   // 46 MB
__device__ __align__(16) float g_z2[(size_t)RR * NN * F2];   // 92 MB
__device__ __align__(16) float g_h[(size_t)NN * F1];         // 15 MB
__device__ __align__(16) float g_el1[RR * NN * 4];
__device__ __align__(16) float g_er1[RR * NN * 4];
__device__ __align__(16) float g_el2[RR * NN * 4];
__device__ __align__(16) float g_er2[RR * NN * 4];
__device__ int g_deg[RR * NN];
__device__ int g_cur[RR * NN];
__device__ int g_rowoff[RR * (NN + 1)];
__device__ int g_col[RR * EE];

__device__ __forceinline__ float lrelu(float x) { return x > 0.f ? x : 0.2f * x; }

// ---------------- CSR build --------------------------------------------------
__global__ void k_zero() {
    int i = blockIdx.x * blockDim.x + threadIdx.x;
    if (i < RR * NN) { g_deg[i] = 0; g_cur[i] = 0; }
}

__global__ void k_hist(const int* __restrict__ dst) {
    int i = blockIdx.x * blockDim.x + threadIdx.x;
    if (i < RR * EE) {
        int r = i / EE;
        atomicAdd(&g_deg[r * NN + dst[i]], 1);
    }
}

__global__ void k_scan() {   // one block per relation; exclusive scan of degrees
    int r = blockIdx.x;
    __shared__ int sh[1024];
    __shared__ int carry;
    int t = threadIdx.x;
    if (t == 0) { carry = 0; g_rowoff[r * (NN + 1)] = 0; }
    __syncthreads();
    for (int base = 0; base < NN; base += 1024) {
        int i = base + t;
        int v = (i < NN) ? g_deg[r * NN + i] : 0;
        sh[t] = v;
        __syncthreads();
        for (int off = 1; off < 1024; off <<= 1) {
            int x = (t >= off) ? sh[t - off] : 0;
            __syncthreads();
            sh[t] += x;
            __syncthreads();
        }
        if (i < NN) g_rowoff[r * (NN + 1) + i + 1] = carry + sh[t];
        __syncthreads();
        if (t == 0) carry += sh[1023];
        __syncthreads();
    }
}

__global__ void k_scatter(const int* __restrict__ src, const int* __restrict__ dst) {
    int i = blockIdx.x * blockDim.x + threadIdx.x;
    if (i < RR * EE) {
        int r = i / EE;
        int d = dst[i];
        int pos = atomicAdd(&g_cur[r * NN + d], 1);
        g_col[(size_t)r * EE + g_rowoff[r * (NN + 1) + d] + pos] = src[i];
    }
}

// ---------------- SGEMM: C[r] = A @ B[r], row-major --------------------------
// 128x128 tile, BK=16, 256 threads, 8x8 microtile (split-quad), double buffered.
__global__ __launch_bounds__(256, 2)
void k_sgemm(const float* __restrict__ Aext, const float* __restrict__ Bg,
             int M, int K, int Nc, int layer) {
    const float* A = (layer == 1) ? Aext : g_h;
    float* C = (layer == 1) ? g_z1 : g_z2;
    int r = blockIdx.z;
    const float* B = Bg + (size_t)r * K * Nc;
    C += (size_t)r * M * Nc;

    __shared__ float As[2][16][132];   // [k][m], padded
    __shared__ float Bs[2][16][128];   // [k][n]

    int tid = threadIdx.x;
    int tx = tid & 15, ty = tid >> 4;
    int row0 = blockIdx.y * 128, col0 = blockIdx.x * 128;

    // A loads: thread -> (row tid>>2 [+64], cols (tid&3)*4 .. +3) of K-slab
    int arow = tid >> 2;
    int acol = (tid & 3) * 4;
    // B loads: thread -> (k tid>>5 [+8], cols (tid&31)*4)
    int brow = tid >> 5;
    int bcol = (tid & 31) * 4;

    float acc[8][8];
#pragma unroll
    for (int i = 0; i < 8; i++)
#pragma unroll
        for (int j = 0; j < 8; j++) acc[i][j] = 0.f;

    // prologue: load k-slab 0 into buffer 0
#pragma unroll
    for (int p = 0; p < 2; p++) {
        int m = arow + p * 64;
        int gr = row0 + m;
        float4 v = (gr < M) ? *reinterpret_cast<const float4*>(&A[(size_t)gr * K + acol])
                            : make_float4(0.f, 0.f, 0.f, 0.f);
        As[0][acol + 0][m] = v.x; As[0][acol + 1][m] = v.y;
        As[0][acol + 2][m] = v.z; As[0][acol + 3][m] = v.w;
    }
#pragma unroll
    for (int p = 0; p < 2; p++) {
        int k = brow + p * 8;
        *reinterpret_cast<float4*>(&Bs[0][k][bcol]) =
            *reinterpret_cast<const float4*>(&B[(size_t)k * Nc + col0 + bcol]);
    }
    __syncthreads();

    int buf = 0;
    for (int k0 = 0; k0 < K; k0 += 16) {
        int nk = k0 + 16;
        if (nk < K) {
#pragma unroll
            for (int p = 0; p < 2; p++) {
                int m = arow + p * 64;
                int gr = row0 + m;
                float4 v = (gr < M) ? *reinterpret_cast<const float4*>(&A[(size_t)gr * K + nk + acol])
                                    : make_float4(0.f, 0.f, 0.f, 0.f);
                As[buf ^ 1][acol + 0][m] = v.x; As[buf ^ 1][acol + 1][m] = v.y;
                As[buf ^ 1][acol + 2][m] = v.z; As[buf ^ 1][acol + 3][m] = v.w;
            }
#pragma unroll
            for (int p = 0; p < 2; p++) {
                int k = brow + p * 8;
                *reinterpret_cast<float4*>(&Bs[buf ^ 1][k][bcol]) =
                    *reinterpret_cast<const float4*>(&B[(size_t)(nk + k) * Nc + col0 + bcol]);
            }
        }
#pragma unroll
        for (int k = 0; k < 16; k++) {
            float a[8], b[8];
            *reinterpret_cast<float4*>(&a[0]) = *reinterpret_cast<float4*>(&As[buf][k][ty * 4]);
            *reinterpret_cast<float4*>(&a[4]) = *reinterpret_cast<float4*>(&As[buf][k][64 + ty * 4]);
            *reinterpret_cast<float4*>(&b[0]) = *reinterpret_cast<float4*>(&Bs[buf][k][tx * 4]);
            *reinterpret_cast<float4*>(&b[4]) = *reinterpret_cast<float4*>(&Bs[buf][k][64 + tx * 4]);
#pragma unroll
            for (int i = 0; i < 8; i++)
#pragma unroll
                for (int j = 0; j < 8; j++) acc[i][j] += a[i] * b[j];
        }
        __syncthreads();
        buf ^= 1;
    }

    // epilogue: rows {ty*4+i, 64+ty*4+i}, cols {tx*4..+3, 64+tx*4..+3}
#pragma unroll
    for (int half = 0; half < 2; half++) {
#pragma unroll
        for (int i = 0; i < 4; i++) {
            int gr = row0 + half * 64 + ty * 4 + i;
            if (gr < M) {
                float* cp = &C[(size_t)gr * Nc + col0];
                int ii = half * 4 + i;
                *reinterpret_cast<float4*>(&cp[tx * 4]) =
                    make_float4(acc[ii][0], acc[ii][1], acc[ii][2], acc[ii][3]);
                *reinterpret_cast<float4*>(&cp[64 + tx * 4]) =
                    make_float4(acc[ii][4], acc[ii][5], acc[ii][6], acc[ii][7]);
            }
        }
    }
}

// ---------------- attention projections (el/er) ------------------------------
__global__ void k_attn1(const float* __restrict__ al, const float* __restrict__ ar) {
    int n = blockIdx.x, r = blockIdx.y;
    int t = threadIdx.x;  // 128
    float z = g_z1[((size_t)(r * NN + n)) * F1 + t];
    float pl = z * al[r * F1 + t];
    float pr = z * ar[r * F1 + t];
#pragma unroll
    for (int o = 16; o > 0; o >>= 1) {
        pl += __shfl_xor_sync(0xffffffffu, pl, o);
        pr += __shfl_xor_sync(0xffffffffu, pr, o);
    }
    if ((t & 31) == 0) {
        int h = t >> 5;
        g_el1[(r * NN + n) * 4 + h] = pl;
        g_er1[(r * NN + n) * 4 + h] = pr;
    }
}

__global__ void k_attn2(const float* __restrict__ al, const float* __restrict__ ar) {
    int n = blockIdx.x, r = blockIdx.y;
    int t = threadIdx.x;  // 256
    float z = g_z2[((size_t)(r * NN + n)) * F2 + t];
    float pl = z * al[r * F2 + t];
    float pr = z * ar[r * F2 + t];
#pragma unroll
    for (int o = 16; o > 0; o >>= 1) {
        pl += __shfl_xor_sync(0xffffffffu, pl, o);
        pr += __shfl_xor_sync(0xffffffffu, pr, o);
    }
    __shared__ float sl[8], sr[8];
    if ((t & 31) == 0) { sl[t >> 5] = pl; sr[t >> 5] = pr; }
    __syncthreads();
    if (t < 4) {
        g_el2[(r * NN + n) * 4 + t] = sl[2 * t] + sl[2 * t + 1];
        g_er2[(r * NN + n) * 4 + t] = sr[2 * t] + sr[2 * t + 1];
    }
}

// ---------------- layer-1 edge softmax + aggregation (warp per dst node) -----
__global__ void k_agg1(const float* __restrict__ b1) {
    int w = (blockIdx.x * blockDim.x + threadIdx.x) >> 5;
    int lane = threadIdx.x & 31;
    if (w >= NN) return;
    int n = w;
    float t0 = 0.f, t1 = 0.f, t2 = 0.f, t3 = 0.f;
#pragma unroll
    for (int r = 0; r < RR; r++) {
        int beg = g_rowoff[r * (NN + 1) + n];
        int end = g_rowoff[r * (NN + 1) + n + 1];
        if (beg == end) continue;
        const float4 erd = *reinterpret_cast<const float4*>(&g_er1[(r * NN + n) * 4]);
        float m0 = -1e30f, m1 = -1e30f, m2 = -1e30f, m3 = -1e30f;
        for (int i = beg; i < end; i++) {
            int s = g_col[(size_t)r * EE + i];
            float4 el = *reinterpret_cast<const float4*>(&g_el1[(r * NN + s) * 4]);
            m0 = fmaxf(m0, lrelu(el.x + erd.x));
            m1 = fmaxf(m1, lrelu(el.y + erd.y));
            m2 = fmaxf(m2, lrelu(el.z + erd.z));
            m3 = fmaxf(m3, lrelu(el.w + erd.w));
        }
        float d0 = 0, d1 = 0, d2 = 0, d3 = 0, a0 = 0, a1 = 0, a2 = 0, a3 = 0;
        for (int i = beg; i < end; i++) {
            int s = g_col[(size_t)r * EE + i];
            float4 el = *reinterpret_cast<const float4*>(&g_el1[(r * NN + s) * 4]);
            float w0 = __expf(lrelu(el.x + erd.x) - m0);
            float w1 = __expf(lrelu(el.y + erd.y) - m1);
            float w2 = __expf(lrelu(el.z + erd.z) - m2);
            float w3 = __expf(lrelu(el.w + erd.w) - m3);
            d0 += w0; d1 += w1; d2 += w2; d3 += w3;
            const float* z = &g_z1[((size_t)(r * NN + s)) * F1];
            a0 += w0 * z[lane];
            a1 += w1 * z[32 + lane];
            a2 += w2 * z[64 + lane];
            a3 += w3 * z[96 + lane];
        }
        t0 += a0 / d0; t1 += a1 / d1; t2 += a2 / d2; t3 += a3 / d3;
    }
    t0 += b1[lane]      + b1[F1 + lane]      + b1[2 * F1 + lane];
    t1 += b1[32 + lane] + b1[F1 + 32 + lane] + b1[2 * F1 + 32 + lane];
    t2 += b1[64 + lane] + b1[F1 + 64 + lane] + b1[2 * F1 + 64 + lane];
    t3 += b1[96 + lane] + b1[F1 + 96 + lane] + b1[2 * F1 + 96 + lane];
    size_t o = (size_t)n * F1;
    g_h[o + lane]      = fmaxf(t0, 0.f);
    g_h[o + 32 + lane] = fmaxf(t1, 0.f);
    g_h[o + 64 + lane] = fmaxf(t2, 0.f);
    g_h[o + 96 + lane] = fmaxf(t3, 0.f);
}

// ---------------- layer-2 edge softmax + aggregation + head mean -------------
__global__ void k_agg2(const float* __restrict__ b2, float* __restrict__ out) {
    int w = (blockIdx.x * blockDim.x + threadIdx.x) >> 5;
    int lane = threadIdx.x & 31;
    if (w >= NN) return;
    int n = w;
    float t00 = 0, t01 = 0, t10 = 0, t11 = 0, t20 = 0, t21 = 0, t30 = 0, t31 = 0;
#pragma unroll
    for (int r = 0; r < RR; r++) {
        int beg = g_rowoff[r * (NN + 1) + n];
        int end = g_rowoff[r * (NN + 1) + n + 1];
        if (beg == end) continue;
        const float4 erd = *reinterpret_cast<const float4*>(&g_er2[(r * NN + n) * 4]);
        float m0 = -1e30f, m1 = -1e30f, m2 = -1e30f, m3 = -1e30f;
        for (int i = beg; i < end; i++) {
            int s = g_col[(size_t)r * EE + i];
            float4 el = *reinterpret_cast<const float4*>(&g_el2[(r * NN + s) * 4]);
            m0 = fmaxf(m0, lrelu(el.x + erd.x));
            m1 = fmaxf(m1, lrelu(el.y + erd.y));
            m2 = fmaxf(m2, lrelu(el.z + erd.z));
            m3 = fmaxf(m3, lrelu(el.w + erd.w));
        }
        float d0 = 0, d1 = 0, d2 = 0, d3 = 0;
        float a00 = 0, a01 = 0, a10 = 0, a11 = 0, a20 = 0, a21 = 0, a30 = 0, a31 = 0;
        for (int i = beg; i < end; i++) {
            int s = g_col[(size_t)r * EE + i];
            float4 el = *reinterpret_cast<const float4*>(&g_el2[(r * NN + s) * 4]);
            float w0 = __expf(lrelu(el.x + erd.x) - m0);
            float w1 = __expf(lrelu(el.y + erd.y) - m1);
            float w2 = __expf(lrelu(el.z + erd.z) - m2);
            float w3 = __expf(lrelu(el.w + erd.w) - m3);
            d0 += w0; d1 += w1; d2 += w2; d3 += w3;
            const float* z = &g_z2[((size_t)(r * NN + s)) * F2];
            a00 += w0 * z[lane];        a01 += w0 * z[32 + lane];
            a10 += w1 * z[64 + lane];   a11 += w1 * z[96 + lane];
            a20 += w2 * z[128 + lane];  a21 += w2 * z[160 + lane];
            a30 += w3 * z[192 + lane];  a31 += w3 * z[224 + lane];
        }
        t00 += a00 / d0; t01 += a01 / d0;
        t10 += a10 / d1; t11 += a11 / d1;
        t20 += a20 / d2; t21 += a21 / d2;
        t30 += a30 / d3; t31 += a31 / d3;
    }
    t00 += b2[lane]       + b2[F2 + lane]       + b2[2 * F2 + lane];
    t01 += b2[32 + lane]  + b2[F2 + 32 + lane]  + b2[2 * F2 + 32 + lane];
    t10 += b2[64 + lane]  + b2[F2 + 64 + lane]  + b2[2 * F2 + 64 + lane];
    t11 += b2[96 + lane]  + b2[F2 + 96 + lane]  + b2[2 * F2 + 96 + lane];
    t20 += b2[128 + lane] + b2[F2 + 128 + lane] + b2[2 * F2 + 128 + lane];
    t21 += b2[160 + lane] + b2[F2 + 160 + lane] + b2[2 * F2 + 160 + lane];
    t30 += b2[192 + lane] + b2[F2 + 192 + lane] + b2[2 * F2 + 192 + lane];
    t31 += b2[224 + lane] + b2[F2 + 224 + lane] + b2[2 * F2 + 224 + lane];
    out[(size_t)n * 64 + lane]      = 0.25f * (t00 + t10 + t20 + t30);
    out[(size_t)n * 64 + 32 + lane] = 0.25f * (t01 + t11 + t21 + t31);
}

// ---------------- launch ------------------------------------------------------
extern "C" void kernel_launch(void* const* d_in, const int* in_sizes, int n_in,
                              void* d_out, int out_size) {
    const float* x   = (const float*)d_in[0];
    const int*   src = (const int*)d_in[1];
    const int*   dst = (const int*)d_in[2];
    const float* W1  = (const float*)d_in[3];
    const float* al1 = (const float*)d_in[4];
    const float* ar1 = (const float*)d_in[5];
    const float* b1  = (const float*)d_in[6];
    const float* W2  = (const float*)d_in[7];
    const float* al2 = (const float*)d_in[8];
    const float* ar2 = (const float*)d_in[9];
    const float* b2  = (const float*)d_in[10];
    float* out = (float*)d_out;

    // CSR by dst, per relation
    k_zero<<<(RR * NN + 255) / 256, 256>>>();
    k_hist<<<(RR * EE + 255) / 256, 256>>>(dst);
    k_scan<<<RR, 1024>>>();
    k_scatter<<<(RR * EE + 255) / 256, 256>>>(src, dst);

    // layer 1
    dim3 g1(F1 / 128, (NN + 127) / 128, RR);
    k_sgemm<<<g1, 256>>>(x, W1, NN, KIN, F1, 1);
    k_attn1<<<dim3(NN, RR), 128>>>(al1, ar1);
    k_agg1<<<(NN + 3) / 4, 128>>>(b1);

    // layer 2
    dim3 g2(F2 / 128, (NN + 127) / 128, RR);
    k_sgemm<<<g2, 256>>>(nullptr, W2, NN, F1, F2, 2);
    k_attn2<<<dim3(NN, RR), 256>>>(al2, ar2);
    k_agg2<<<(NN + 3) / 4, 128>>>(b2, out);
}

// round 4
// speedup vs baseline: 1.5766x; 1.3368x over previous
#include <cuda_runtime.h>
#include <math.h>

#define NN 30000
#define EE 300000
#define RR 3
#define KIN 256
#define F1 128   // HEADS*HID
#define F2 256   // HEADS*OUT

// ---------------- scratch (device globals; no allocation allowed) ----------
__device__ __align__(16) float g_z1[(size_t)RR * NN * F1];   // 46 MB
__device__ __align__(16) float g_z2[(size_t)RR * NN * F2];   // 92 MB
__device__ __align__(16) float g_h[(size_t)NN * F1];         // 15 MB
__device__ __align__(16) float g_el1[RR * NN * 4];
__device__ __align__(16) float g_er1[RR * NN * 4];
__device__ __align__(16) float g_el2[RR * NN * 4];
__device__ __align__(16) float g_er2[RR * NN * 4];
__device__ int g_deg[RR * NN];
__device__ int g_cur[RR * NN];
__device__ int g_rowoff[RR * (NN + 1)];
__device__ int g_col[RR * EE];

__device__ __forceinline__ float lrelu(float x) { return x > 0.f ? x : 0.2f * x; }

__device__ __forceinline__ unsigned f2tf32(float v) {
    unsigned u;
    asm("cvt.rna.tf32.f32 %0, %1;" : "=r"(u) : "f"(v));
    return u;
}

// ---------------- CSR build --------------------------------------------------
__global__ void k_zero() {
    int i = blockIdx.x * blockDim.x + threadIdx.x;
    if (i < RR * NN) { g_deg[i] = 0; g_cur[i] = 0; }
}

__global__ void k_hist(const int* __restrict__ dst) {
    int i = blockIdx.x * blockDim.x + threadIdx.x;
    if (i < RR * EE) {
        int r = i / EE;
        atomicAdd(&g_deg[r * NN + dst[i]], 1);
    }
}

__global__ void k_scan() {
    int r = blockIdx.x;
    __shared__ int sh[1024];
    __shared__ int carry;
    int t = threadIdx.x;
    if (t == 0) { carry = 0; g_rowoff[r * (NN + 1)] = 0; }
    __syncthreads();
    for (int base = 0; base < NN; base += 1024) {
        int i = base + t;
        int v = (i < NN) ? g_deg[r * NN + i] : 0;
        sh[t] = v;
        __syncthreads();
        for (int off = 1; off < 1024; off <<= 1) {
            int x = (t >= off) ? sh[t - off] : 0;
            __syncthreads();
            sh[t] += x;
            __syncthreads();
        }
        if (i < NN) g_rowoff[r * (NN + 1) + i + 1] = carry + sh[t];
        __syncthreads();
        if (t == 0) carry += sh[1023];
        __syncthreads();
    }
}

__global__ void k_scatter(const int* __restrict__ src, const int* __restrict__ dst) {
    int i = blockIdx.x * blockDim.x + threadIdx.x;
    if (i < RR * EE) {
        int r = i / EE;
        int d = dst[i];
        int pos = atomicAdd(&g_cur[r * NN + d], 1);
        g_col[(size_t)r * EE + g_rowoff[r * (NN + 1) + d] + pos] = src[i];
    }
}

// ---------------- TF32 tensor-core GEMM: C[r] = A @ B[r] ---------------------
// Block 128x128, 8 warps (2x4), warp tile 64x32, mma.m16n8k8.tf32, BK=16.
// smem k-major with stride 132 -> conflict-free fragment loads (banks 4c+r).
#define SSTR 132

__global__ __launch_bounds__(256, 2)
void k_sgemm_tf32(const float* __restrict__ Aext, const float* __restrict__ Bg,
                  int M, int K, int Nc, int layer) {
    const float* A = (layer == 1) ? Aext : g_h;
    float* C = (layer == 1) ? g_z1 : g_z2;
    int r = blockIdx.z;
    const float* B = Bg + (size_t)r * K * Nc;
    C += (size_t)r * M * Nc;

    __shared__ unsigned As[2][16 * SSTR];   // [k][m]
    __shared__ unsigned Bs[2][16 * SSTR];   // [k][n]

    int tid = threadIdx.x;
    int lane = tid & 31;
    int wid = tid >> 5;
    int wm = (wid & 1) * 64;       // warp m offset
    int wn = (wid >> 1) * 32;      // warp n offset
    int gid = lane >> 2;           // groupID
    int tig = lane & 3;            // thread-in-group

    int row0 = blockIdx.y * 128, col0 = blockIdx.x * 128;

    // A loads: thread -> rows (tid>>2), (tid>>2)+64 ; k-cols (tid&3)*4..+3
    int am = tid >> 2;
    int ak = (tid & 3) * 4;
    // B loads: thread -> k row tid>>4 ; n cols (tid&15)*4 and 64+(tid&15)*4
    int bk = tid >> 4;
    int bn = (tid & 15) * 4;

    float acc[4][4][4];
#pragma unroll
    for (int i = 0; i < 4; i++)
#pragma unroll
        for (int j = 0; j < 4; j++)
#pragma unroll
            for (int q = 0; q < 4; q++) acc[i][j][q] = 0.f;

    int nstage = K >> 4;

    // prologue: stage 0
    {
        float4 va0, va1, vb0, vb1;
        int gr0 = row0 + am, gr1 = row0 + am + 64;
        va0 = (gr0 < M) ? *reinterpret_cast<const float4*>(&A[(size_t)gr0 * K + ak])
                        : make_float4(0, 0, 0, 0);
        va1 = (gr1 < M) ? *reinterpret_cast<const float4*>(&A[(size_t)gr1 * K + ak])
                        : make_float4(0, 0, 0, 0);
        vb0 = *reinterpret_cast<const float4*>(&B[(size_t)bk * Nc + col0 + bn]);
        vb1 = *reinterpret_cast<const float4*>(&B[(size_t)bk * Nc + col0 + 64 + bn]);
        As[0][(ak + 0) * SSTR + am] = f2tf32(va0.x);
        As[0][(ak + 1) * SSTR + am] = f2tf32(va0.y);
        As[0][(ak + 2) * SSTR + am] = f2tf32(va0.z);
        As[0][(ak + 3) * SSTR + am] = f2tf32(va0.w);
        As[0][(ak + 0) * SSTR + am + 64] = f2tf32(va1.x);
        As[0][(ak + 1) * SSTR + am + 64] = f2tf32(va1.y);
        As[0][(ak + 2) * SSTR + am + 64] = f2tf32(va1.z);
        As[0][(ak + 3) * SSTR + am + 64] = f2tf32(va1.w);
        Bs[0][bk * SSTR + bn + 0] = f2tf32(vb0.x);
        Bs[0][bk * SSTR + bn + 1] = f2tf32(vb0.y);
        Bs[0][bk * SSTR + bn + 2] = f2tf32(vb0.z);
        Bs[0][bk * SSTR + bn + 3] = f2tf32(vb0.w);
        Bs[0][bk * SSTR + 64 + bn + 0] = f2tf32(vb1.x);
        Bs[0][bk * SSTR + 64 + bn + 1] = f2tf32(vb1.y);
        Bs[0][bk * SSTR + 64 + bn + 2] = f2tf32(vb1.z);
        Bs[0][bk * SSTR + 64 + bn + 3] = f2tf32(vb1.w);
    }
    __syncthreads();

    int buf = 0;
    for (int s = 0; s < nstage; s++) {
        float4 va0, va1, vb0, vb1;
        bool more = (s + 1) < nstage;
        if (more) {
            int k0 = (s + 1) << 4;
            int gr0 = row0 + am, gr1 = row0 + am + 64;
            va0 = (gr0 < M) ? *reinterpret_cast<const float4*>(&A[(size_t)gr0 * K + k0 + ak])
                            : make_float4(0, 0, 0, 0);
            va1 = (gr1 < M) ? *reinterpret_cast<const float4*>(&A[(size_t)gr1 * K + k0 + ak])
                            : make_float4(0, 0, 0, 0);
            vb0 = *reinterpret_cast<const float4*>(&B[(size_t)(k0 + bk) * Nc + col0 + bn]);
            vb1 = *reinterpret_cast<const float4*>(&B[(size_t)(k0 + bk) * Nc + col0 + 64 + bn]);
        }

        const unsigned* as = As[buf];
        const unsigned* bs = Bs[buf];
#pragma unroll
        for (int kk = 0; kk < 16; kk += 8) {
            unsigned a[4][4], b[4][2];
#pragma unroll
            for (int i = 0; i < 4; i++) {
                int m = wm + i * 16 + gid;
                a[i][0] = as[(kk + tig) * SSTR + m];
                a[i][1] = as[(kk + tig) * SSTR + m + 8];
                a[i][2] = as[(kk + tig + 4) * SSTR + m];
                a[i][3] = as[(kk + tig + 4) * SSTR + m + 8];
            }
#pragma unroll
            for (int j = 0; j < 4; j++) {
                int n = wn + j * 8 + gid;
                b[j][0] = bs[(kk + tig) * SSTR + n];
                b[j][1] = bs[(kk + tig + 4) * SSTR + n];
            }
#pragma unroll
            for (int i = 0; i < 4; i++)
#pragma unroll
                for (int j = 0; j < 4; j++) {
                    asm volatile(
                        "mma.sync.aligned.m16n8k8.row.col.f32.tf32.tf32.f32 "
                        "{%0,%1,%2,%3}, {%4,%5,%6,%7}, {%8,%9}, {%0,%1,%2,%3};\n"
                        : "+f"(acc[i][j][0]), "+f"(acc[i][j][1]),
                          "+f"(acc[i][j][2]), "+f"(acc[i][j][3])
                        : "r"(a[i][0]), "r"(a[i][1]), "r"(a[i][2]), "r"(a[i][3]),
                          "r"(b[j][0]), "r"(b[j][1]));
                }
        }

        if (more) {
            unsigned* asn = As[buf ^ 1];
            unsigned* bsn = Bs[buf ^ 1];
            asn[(ak + 0) * SSTR + am] = f2tf32(va0.x);
            asn[(ak + 1) * SSTR + am] = f2tf32(va0.y);
            asn[(ak + 2) * SSTR + am] = f2tf32(va0.z);
            asn[(ak + 3) * SSTR + am] = f2tf32(va0.w);
            asn[(ak + 0) * SSTR + am + 64] = f2tf32(va1.x);
            asn[(ak + 1) * SSTR + am + 64] = f2tf32(va1.y);
            asn[(ak + 2) * SSTR + am + 64] = f2tf32(va1.z);
            asn[(ak + 3) * SSTR + am + 64] = f2tf32(va1.w);
            bsn[bk * SSTR + bn + 0] = f2tf32(vb0.x);
            bsn[bk * SSTR + bn + 1] = f2tf32(vb0.y);
            bsn[bk * SSTR + bn + 2] = f2tf32(vb0.z);
            bsn[bk * SSTR + bn + 3] = f2tf32(vb0.w);
            bsn[bk * SSTR + 64 + bn + 0] = f2tf32(vb1.x);
            bsn[bk * SSTR + 64 + bn + 1] = f2tf32(vb1.y);
            bsn[bk * SSTR + 64 + bn + 2] = f2tf32(vb1.z);
            bsn[bk * SSTR + 64 + bn + 3] = f2tf32(vb1.w);
        }
        __syncthreads();
        buf ^= 1;
    }

    // epilogue
#pragma unroll
    for (int i = 0; i < 4; i++) {
#pragma unroll
        for (int j = 0; j < 4; j++) {
            int gr = row0 + wm + i * 16 + gid;
            int gc = col0 + wn + j * 8 + 2 * tig;
            if (gr < M)
                *reinterpret_cast<float2*>(&C[(size_t)gr * Nc + gc]) =
                    make_float2(acc[i][j][0], acc[i][j][1]);
            if (gr + 8 < M)
                *reinterpret_cast<float2*>(&C[(size_t)(gr + 8) * Nc + gc]) =
                    make_float2(acc[i][j][2], acc[i][j][3]);
        }
    }
}

// ---------------- attention projections (el/er) ------------------------------
__global__ void k_attn1(const float* __restrict__ al, const float* __restrict__ ar) {
    int n = blockIdx.x, r = blockIdx.y;
    int t = threadIdx.x;  // 128
    float z = g_z1[((size_t)(r * NN + n)) * F1 + t];
    float pl = z * al[r * F1 + t];
    float pr = z * ar[r * F1 + t];
#pragma unroll
    for (int o = 16; o > 0; o >>= 1) {
        pl += __shfl_xor_sync(0xffffffffu, pl, o);
        pr += __shfl_xor_sync(0xffffffffu, pr, o);
    }
    if ((t & 31) == 0) {
        int h = t >> 5;
        g_el1[(r * NN + n) * 4 + h] = pl;
        g_er1[(r * NN + n) * 4 + h] = pr;
    }
}

__global__ void k_attn2(const float* __restrict__ al, const float* __restrict__ ar) {
    int n = blockIdx.x, r = blockIdx.y;
    int t = threadIdx.x;  // 256
    float z = g_z2[((size_t)(r * NN + n)) * F2 + t];
    float pl = z * al[r * F2 + t];
    float pr = z * ar[r * F2 + t];
#pragma unroll
    for (int o = 16; o > 0; o >>= 1) {
        pl += __shfl_xor_sync(0xffffffffu, pl, o);
        pr += __shfl_xor_sync(0xffffffffu, pr, o);
    }
    __shared__ float sl[8], sr[8];
    if ((t & 31) == 0) { sl[t >> 5] = pl; sr[t >> 5] = pr; }
    __syncthreads();
    if (t < 4) {
        g_el2[(r * NN + n) * 4 + t] = sl[2 * t] + sl[2 * t + 1];
        g_er2[(r * NN + n) * 4 + t] = sr[2 * t] + sr[2 * t + 1];
    }
}

// ---------------- layer-1 edge softmax + aggregation (warp per dst node) -----
// single pass: softmax without max-shift (shift invariant; |e| is small)
__global__ void k_agg1(const float* __restrict__ b1) {
    int w = (blockIdx.x * blockDim.x + threadIdx.x) >> 5;
    int lane = threadIdx.x & 31;
    if (w >= NN) return;
    int n = w;
    float t0 = 0.f, t1 = 0.f, t2 = 0.f, t3 = 0.f;
#pragma unroll
    for (int r = 0; r < RR; r++) {
        int beg = g_rowoff[r * (NN + 1) + n];
        int end = g_rowoff[r * (NN + 1) + n + 1];
        if (beg == end) continue;
        const float4 erd = *reinterpret_cast<const float4*>(&g_er1[(r * NN + n) * 4]);
        float d0 = 0, d1 = 0, d2 = 0, d3 = 0, a0 = 0, a1 = 0, a2 = 0, a3 = 0;
        for (int i = beg; i < end; i++) {
            int s = g_col[(size_t)r * EE + i];
            float4 el = *reinterpret_cast<const float4*>(&g_el1[(r * NN + s) * 4]);
            float w0 = __expf(lrelu(el.x + erd.x));
            float w1 = __expf(lrelu(el.y + erd.y));
            float w2 = __expf(lrelu(el.z + erd.z));
            float w3 = __expf(lrelu(el.w + erd.w));
            d0 += w0; d1 += w1; d2 += w2; d3 += w3;
            const float* z = &g_z1[((size_t)(r * NN + s)) * F1];
            a0 += w0 * z[lane];
            a1 += w1 * z[32 + lane];
            a2 += w2 * z[64 + lane];
            a3 += w3 * z[96 + lane];
        }
        t0 += a0 / d0; t1 += a1 / d1; t2 += a2 / d2; t3 += a3 / d3;
    }
    t0 += b1[lane]      + b1[F1 + lane]      + b1[2 * F1 + lane];
    t1 += b1[32 + lane] + b1[F1 + 32 + lane] + b1[2 * F1 + 32 + lane];
    t2 += b1[64 + lane] + b1[F1 + 64 + lane] + b1[2 * F1 + 64 + lane];
    t3 += b1[96 + lane] + b1[F1 + 96 + lane] + b1[2 * F1 + 96 + lane];
    size_t o = (size_t)n * F1;
    g_h[o + lane]      = fmaxf(t0, 0.f);
    g_h[o + 32 + lane] = fmaxf(t1, 0.f);
    g_h[o + 64 + lane] = fmaxf(t2, 0.f);
    g_h[o + 96 + lane] = fmaxf(t3, 0.f);
}

// ---------------- layer-2 edge softmax + aggregation + head mean -------------
__global__ void k_agg2(const float* __restrict__ b2, float* __restrict__ out) {
    int w = (blockIdx.x * blockDim.x + threadIdx.x) >> 5;
    int lane = threadIdx.x & 31;
    if (w >= NN) return;
    int n = w;
    float t00 = 0, t01 = 0, t10 = 0, t11 = 0, t20 = 0, t21 = 0, t30 = 0, t31 = 0;
#pragma unroll
    for (int r = 0; r < RR; r++) {
        int beg = g_rowoff[r * (NN + 1) + n];
        int end = g_rowoff[r * (NN + 1) + n + 1];
        if (beg == end) continue;
        const float4 erd = *reinterpret_cast<const float4*>(&g_er2[(r * NN + n) * 4]);
        float d0 = 0, d1 = 0, d2 = 0, d3 = 0;
        float a00 = 0, a01 = 0, a10 = 0, a11 = 0, a20 = 0, a21 = 0, a30 = 0, a31 = 0;
        for (int i = beg; i < end; i++) {
            int s = g_col[(size_t)r * EE + i];
            float4 el = *reinterpret_cast<const float4*>(&g_el2[(r * NN + s) * 4]);
            float w0 = __expf(lrelu(el.x + erd.x));
            float w1 = __expf(lrelu(el.y + erd.y));
            float w2 = __expf(lrelu(el.z + erd.z));
            float w3 = __expf(lrelu(el.w + erd.w));
            d0 += w0; d1 += w1; d2 += w2; d3 += w3;
            const float* z = &g_z2[((size_t)(r * NN + s)) * F2];
            a00 += w0 * z[lane];        a01 += w0 * z[32 + lane];
            a10 += w1 * z[64 + lane];   a11 += w1 * z[96 + lane];
            a20 += w2 * z[128 + lane];  a21 += w2 * z[160 + lane];
            a30 += w3 * z[192 + lane];  a31 += w3 * z[224 + lane];
        }
        t00 += a00 / d0; t01 += a01 / d0;
        t10 += a10 / d1; t11 += a11 / d1;
        t20 += a20 / d2; t21 += a21 / d2;
        t30 += a30 / d3; t31 += a31 / d3;
    }
    t00 += b2[lane]       + b2[F2 + lane]       + b2[2 * F2 + lane];
    t01 += b2[32 + lane]  + b2[F2 + 32 + lane]  + b2[2 * F2 + 32 + lane];
    t10 += b2[64 + lane]  + b2[F2 + 64 + lane]  + b2[2 * F2 + 64 + lane];
    t11 += b2[96 + lane]  + b2[F2 + 96 + lane]  + b2[2 * F2 + 96 + lane];
    t20 += b2[128 + lane] + b2[F2 + 128 + lane] + b2[2 * F2 + 128 + lane];
    t21 += b2[160 + lane] + b2[F2 + 160 + lane] + b2[2 * F2 + 160 + lane];
    t30 += b2[192 + lane] + b2[F2 + 192 + lane] + b2[2 * F2 + 192 + lane];
    t31 += b2[224 + lane] + b2[F2 + 224 + lane] + b2[2 * F2 + 224 + lane];
    out[(size_t)n * 64 + lane]      = 0.25f * (t00 + t10 + t20 + t30);
    out[(size_t)n * 64 + 32 + lane] = 0.25f * (t01 + t11 + t21 + t31);
}

// ---------------- launch ------------------------------------------------------
extern "C" void kernel_launch(void* const* d_in, const int* in_sizes, int n_in,
                              void* d_out, int out_size) {
    const float* x   = (const float*)d_in[0];
    const int*   src = (const int*)d_in[1];
    const int*   dst = (const int*)d_in[2];
    const float* W1  = (const float*)d_in[3];
    const float* al1 = (const float*)d_in[4];
    const float* ar1 = (const float*)d_in[5];
    const float* b1  = (const float*)d_in[6];
    const float* W2  = (const float*)d_in[7];
    const float* al2 = (const float*)d_in[8];
    const float* ar2 = (const float*)d_in[9];
    const float* b2  = (const float*)d_in[10];
    float* out = (float*)d_out;

    // CSR by dst, per relation
    k_zero<<<(RR * NN + 255) / 256, 256>>>();
    k_hist<<<(RR * EE + 255) / 256, 256>>>(dst);
    k_scan<<<RR, 1024>>>();
    k_scatter<<<(RR * EE + 255) / 256, 256>>>(src, dst);

    // layer 1
    dim3 g1(F1 / 128, (NN + 127) / 128, RR);
    k_sgemm_tf32<<<g1, 256>>>(x, W1, NN, KIN, F1, 1);
    k_attn1<<<dim3(NN, RR), 128>>>(al1, ar1);
    k_agg1<<<(NN + 3) / 4, 128>>>(b1);

    // layer 2
    dim3 g2(F2 / 128, (NN + 127) / 128, RR);
    k_sgemm_tf32<<<g2, 256>>>(nullptr, W2, NN, F1, F2, 2);
    k_attn2<<<dim3(NN, RR), 256>>>(al2, ar2);
    k_agg2<<<(NN + 3) / 4, 128>>>(b2, out);
}